// round 2
// baseline (speedup 1.0000x reference)
#include <cuda_runtime.h>
#include <cstdint>

// Problem constants
#define ND 729      // detectors
#define NA 180      // angles
#define NB 2        // batch
#define NH 512
#define NW 512

#define PI_D 3.141592653589793

// Scratch (no cudaMalloc allowed)
__device__ float g_h2[2 * ND];        // circular-conv kernel, duplicated (index by d+ND)
__device__ float g_cas[NA];           // cos(angle) * D/(2pi)
__device__ float g_sas[NA];           // sin(angle) * D/(2pi)
__device__ float g_filt[NB * NA * ND];

// ---------------------------------------------------------------------------
// Kernel 1: precompute spatial filter h2 and scaled trig tables.
// h[d] = (1/D) * ( F[0] + sum_{k odd} F[k] * cos(2*pi*k*d/D) ),  F[0]=0.25,
// F[k]=-1/(pi^2 k^2) for odd k. Exact integer range reduction: angle in pi
// units = (2*k*d mod 2D)/D, so cospif sees a small, precise argument.
// ---------------------------------------------------------------------------
__global__ void k_precompute() {
    int n = blockIdx.x * blockDim.x + threadIdx.x;
    if (n < 2 * ND) {
        const float inv_pi2 = (float)(1.0 / (PI_D * PI_D));
        float sum = 0.25f;
        int m2 = (2 * n) % (2 * ND);          // (2*k*n) mod 2D at k=1
        int delta = (4 * n) % (2 * ND);       // step per k += 2
        for (int k = 1; k < ND; k += 2) {
            float c = cospif((float)m2 * (1.0f / 729.0f));
            float w = -inv_pi2 / (float)(k * k);
            sum = fmaf(w, c, sum);
            m2 += delta;
            if (m2 >= 2 * ND) m2 -= 2 * ND;
        }
        g_h2[n] = sum * (1.0f / 729.0f);
    } else if (n < 2 * ND + NA) {
        int a = n - 2 * ND;
        double ang = (double)a * (PI_D / (double)(NA - 1));  // linspace(0, pi, 180) inclusive
        double S = (double)ND / (2.0 * PI_D);
        g_cas[a] = (float)(cos(ang) * S);
        g_sas[a] = (float)(sin(ang) * S);
    }
}

// ---------------------------------------------------------------------------
// Kernel 2: per-row circular convolution. One block per (b, a) row.
// filtered[n] = sum_m s[m] * h[(n - m) mod D] = sum_m s[m] * h2[n - m + D]
// ---------------------------------------------------------------------------
__global__ void __launch_bounds__(736) k_filter(const float* __restrict__ sino) {
    __shared__ float s_sh[ND];
    __shared__ float h_sh[2 * ND];

    int row = blockIdx.x;  // b*NA + a
    const float* src = sino + row * ND;
    for (int i = threadIdx.x; i < ND; i += blockDim.x) s_sh[i] = src[i];
    for (int i = threadIdx.x; i < 2 * ND; i += blockDim.x) h_sh[i] = g_h2[i];
    __syncthreads();

    int n = threadIdx.x;
    if (n < ND) {
        const float* hn = h_sh + n + ND;  // read hn[-m]
        float acc = 0.0f;
        #pragma unroll 8
        for (int m = 0; m < ND; m++) {
            acc = fmaf(s_sh[m], hn[-m], acc);
        }
        g_filt[row * ND + n] = acc;
    }
}

// ---------------------------------------------------------------------------
// Kernel 3: backprojection. One thread per output pixel, loop over angles.
// t = (xc*cos + yc*sin) * D/(2pi); idx = clip(trunc(t), 0, D-1)
//   == (int)(fminf(fmaxf(t,0), 728))   (trunc-toward-zero equivalence)
// ---------------------------------------------------------------------------
__global__ void __launch_bounds__(256) k_backproj(float* __restrict__ out) {
    __shared__ float cas[NA];
    __shared__ float sas[NA];
    int tid = threadIdx.x;
    if (tid < NA) { cas[tid] = g_cas[tid]; sas[tid] = g_sas[tid]; }
    __syncthreads();

    int p = blockIdx.x * blockDim.x + tid;
    if (p >= NB * NH * NW) return;
    int b = p >> 18;              // / (512*512)
    int rem = p & (NH * NW - 1);
    int y = rem >> 9;             // / 512
    int x = rem & (NW - 1);

    float xc = (float)x - (float)(NW / 2);
    float yc = (float)y - (float)(NH / 2);

    const float* base = g_filt + b * (NA * ND);
    float acc = 0.0f;
    #pragma unroll 4
    for (int a = 0; a < NA; a++) {
        float t = fmaf(yc, sas[a], xc * cas[a]);
        t = fminf(fmaxf(t, 0.0f), (float)(ND - 1));
        int idx = (int)t;
        acc += __ldg(base + a * ND + idx);
    }
    // clip(recon, 0, recon.max()) == relu since global max > 0 for this input
    out[p] = fmaxf(acc * (float)(PI_D / (double)NA), 0.0f);
}

// ---------------------------------------------------------------------------
extern "C" void kernel_launch(void* const* d_in, const int* in_sizes, int n_in,
                              void* d_out, int out_size) {
    const float* sino = (const float*)d_in[0];
    float* out = (float*)d_out;

    int pre_threads = 2 * ND + NA;  // 1638
    k_precompute<<<(pre_threads + 255) / 256, 256>>>();
    k_filter<<<NB * NA, 736>>>(sino);
    k_backproj<<<(NB * NH * NW + 255) / 256, 256>>>(out);
}

// round 4
// speedup vs baseline: 1.5308x; 1.5308x over previous
#include <cuda_runtime.h>
#include <cstdint>

#define ND 729
#define NA 180
#define NB 2
#define NH 512
#define NW 512
#define PI_D 3.141592653589793

// Scratch
__device__ float g_h[368];              // h(d), d=0..364 (symmetric core)
__device__ float g_cs[2 * NA];          // interleaved {cos*S, sin*S}
__device__ float g_filt[NB * NA * ND];

// ---------------------------------------------------------------------------
// Kernel 1: precompute. Blocks 0..45: warp-per-output h(d), d = blk*8 + warp.
// h(d) = (1/729)(0.25 - (1/pi^2) * sum_{k odd<=727} cos(2*pi*k*d/729)/k^2)
// Block 46: angle trig tables (double precision, one lane each).
// ---------------------------------------------------------------------------
__global__ void __launch_bounds__(256) k_pre() {
    if (blockIdx.x == 46) {
        int a = threadIdx.x;
        if (a < NA) {
            double ang = (double)a * (PI_D / 179.0);
            double S = 729.0 / (2.0 * PI_D);
            g_cs[2 * a + 0] = (float)(cos(ang) * S);
            g_cs[2 * a + 1] = (float)(sin(ang) * S);
        }
        return;
    }
    int w = threadIdx.x >> 5;
    int lane = threadIdx.x & 31;
    int n = blockIdx.x * 8 + w;           // 0..367 (use <=364)
    float part = 0.0f;
    for (int j = lane; j < 364; j += 32) {
        int k = 2 * j + 1;                 // odd 1..727
        int m = (n * k) % ND;              // exact integer range reduction
        float c = cospif((float)m * (2.0f / 729.0f));
        part += __fdividef(c, (float)(k * k));
    }
    #pragma unroll
    for (int o = 16; o; o >>= 1) part += __shfl_xor_sync(0xffffffffu, part, o);
    if (lane == 0 && n <= 364) {
        const float inv_pi2 = (float)(1.0 / (PI_D * PI_D));
        g_h[n] = (0.25f - inv_pi2 * part) * (1.0f / 729.0f);
    }
}

// ---------------------------------------------------------------------------
// Kernel 2: circular convolution, register-tiled 7 outputs x 8 taps.
// out[n] = sum_m s[m] * h2[n - m + 729],  h2[j] = h(fold(j mod 729))
// Thread t (t<105) computes outputs 7t..7t+6. Window w[j]=h_sh[7t+722-m0+j].
// ---------------------------------------------------------------------------
__global__ void __launch_bounds__(128) k_filter(const float* __restrict__ sino) {
    __shared__ float s_sh[736];
    __shared__ float h_sh[1536];

    int tid = threadIdx.x;
    int row = blockIdx.x;                  // b*NA + a
    const float* src = sino + row * ND;
    for (int i = tid; i < ND; i += 128) s_sh[i] = src[i];
    for (int i = tid; i < 1536; i += 128) {
        float v = 0.0f;
        if (i < 2 * ND) {
            int d = (i < ND) ? i : i - ND;
            if (d > 364) d = ND - d;
            v = g_h[d];
        }
        h_sh[i] = v;
    }
    __syncthreads();

    if (tid < 105) {
        int nb = 7 * tid;
        float acc0 = 0.f, acc1 = 0.f, acc2 = 0.f, acc3 = 0.f, acc4 = 0.f, acc5 = 0.f, acc6 = 0.f;
        const float4* s4 = (const float4*)s_sh;
        for (int c = 0; c < 91; c++) {
            int m0 = c * 8;
            float4 sA = s4[2 * c];
            float4 sB = s4[2 * c + 1];
            float w[14];
            int base = nb + 722 - m0;
            #pragma unroll
            for (int j = 0; j < 14; j++) w[j] = h_sh[base + j];
            float sk[8] = {sA.x, sA.y, sA.z, sA.w, sB.x, sB.y, sB.z, sB.w};
            #pragma unroll
            for (int k = 0; k < 8; k++) {
                acc0 = fmaf(sk[k], w[7 - k], acc0);
                acc1 = fmaf(sk[k], w[8 - k], acc1);
                acc2 = fmaf(sk[k], w[9 - k], acc2);
                acc3 = fmaf(sk[k], w[10 - k], acc3);
                acc4 = fmaf(sk[k], w[11 - k], acc4);
                acc5 = fmaf(sk[k], w[12 - k], acc5);
                acc6 = fmaf(sk[k], w[13 - k], acc6);
            }
        }
        // tail tap m = 728: h2 index = nb + i + 1
        float st = s_sh[728];
        acc0 = fmaf(st, h_sh[nb + 1], acc0);
        acc1 = fmaf(st, h_sh[nb + 2], acc1);
        acc2 = fmaf(st, h_sh[nb + 3], acc2);
        acc3 = fmaf(st, h_sh[nb + 4], acc3);
        acc4 = fmaf(st, h_sh[nb + 5], acc4);
        acc5 = fmaf(st, h_sh[nb + 6], acc5);
        acc6 = fmaf(st, h_sh[nb + 7], acc6);

        float* dst = g_filt + row * ND + nb;
        float accs[7] = {acc0, acc1, acc2, acc3, acc4, acc5, acc6};
        #pragma unroll
        for (int i = 0; i < 7; i++)
            if (nb + i < ND) dst[i] = accs[i];
    }
}

// ---------------------------------------------------------------------------
// Kernel 3: backprojection. Thread handles 4 y-consecutive pixels for BOTH
// batches. t(y) = fma(yc, sin*S, xc*cos*S) is monotone-increasing in y
// (sin >= ~0), so endpoint tests with 0.5 safety margin classify the group:
//   t(y3) <= 0.5   -> all idx 0   (add f[a,0] once to common acc)
//   t(y0) >= 728.5 -> all idx 728 (add f[a,728] once)
//   else exact per-y path (rare strip/boundary).
// ---------------------------------------------------------------------------
__global__ void __launch_bounds__(256) k_backproj(float* __restrict__ out) {
    __shared__ float2 cs[NA];
    __shared__ float f0b0[NA], f7b0[NA], f0b1[NA], f7b1[NA];
    int tid = threadIdx.x;
    for (int i = tid; i < NA; i += 256) {
        cs[i] = ((const float2*)g_cs)[i];
        f0b0[i] = g_filt[i * ND];
        f7b0[i] = g_filt[i * ND + 728];
        f0b1[i] = g_filt[NA * ND + i * ND];
        f7b1[i] = g_filt[NA * ND + i * ND + 728];
    }
    __syncthreads();

    int gid = blockIdx.x * 256 + tid;     // 0..65535 (one per x * y-group)
    int x = gid & (NW - 1);
    int yg = gid >> 9;                     // 0..127
    if (yg >= NH / 4) return;              // guard against grid oversubscription
    int y0 = yg * 4;

    float xc = (float)x - 256.0f;
    float yc0 = (float)y0 - 256.0f;

    float accC0 = 0.f, accC1 = 0.f;
    float ay0[4] = {0.f, 0.f, 0.f, 0.f};
    float ay1[4] = {0.f, 0.f, 0.f, 0.f};

    const float* base0 = g_filt;
    const float* base1 = g_filt + NA * ND;

    for (int a = 0; a < NA; a++) {
        float2 t2 = cs[a];
        float xcc = xc * t2.x;
        float t0 = fmaf(yc0, t2.y, xcc);
        float t3 = fmaf(yc0 + 3.0f, t2.y, xcc);
        if (t3 <= 0.5f) {
            accC0 += f0b0[a];
            accC1 += f0b1[a];
        } else if (t0 >= 728.5f) {
            accC0 += f7b0[a];
            accC1 += f7b1[a];
        } else {
            const float* r0 = base0 + a * ND;
            const float* r1 = base1 + a * ND;
            #pragma unroll
            for (int yy = 0; yy < 4; yy++) {
                float tt = fmaf(yc0 + (float)yy, t2.y, xcc);
                tt = fminf(fmaxf(tt, 0.0f), 728.0f);
                int idx = (int)tt;
                ay0[yy] += __ldg(r0 + idx);
                ay1[yy] += __ldg(r1 + idx);
            }
        }
    }

    const float scale = (float)(PI_D / (double)NA);
    #pragma unroll
    for (int yy = 0; yy < 4; yy++) {
        int p = (y0 + yy) * NW + x;
        out[p] = fmaxf((accC0 + ay0[yy]) * scale, 0.0f);
        out[NH * NW + p] = fmaxf((accC1 + ay1[yy]) * scale, 0.0f);
    }
}

// ---------------------------------------------------------------------------
extern "C" void kernel_launch(void* const* d_in, const int* in_sizes, int n_in,
                              void* d_out, int out_size) {
    const float* sino = (const float*)d_in[0];
    float* out = (float*)d_out;

    k_pre<<<47, 256>>>();
    k_filter<<<NB * NA, 128>>>(sino);
    // one thread per (x, y-group-of-4); each thread covers both batches:
    // 512 * (512/4) = 65536 threads -> 256 blocks of 256
    k_backproj<<<(NW * (NH / 4)) / 256, 256>>>(out);
}

// round 6
// speedup vs baseline: 3.6004x; 2.3520x over previous
#include <cuda_runtime.h>
#include <cstdint>

#define ND 729
#define NA 180
#define NB 2
#define NH 512
#define NW 512
#define PI_D 3.141592653589793

// Scratch (no cudaMalloc allowed)
__device__ float  g_filt[NB * NA * ND];
__device__ float2 g_cs[NA];            // (cos*S, sin*S), S = 729/(2*pi)
__device__ float  g_P0[NB][NA + 1];    // exclusive prefix of f[b][a][0]   over a
__device__ float  g_P7[NB][NA + 1];    // exclusive prefix of f[b][a][728] over a

// ---------------------------------------------------------------------------
// Kernel 1: filter. Effective conv kernel is closed-form piecewise-linear:
//   h(d) = (1/729)*(1/8 + min(d, 729-d)/1458)
// so out[n] = c0*T + c1*W[n] where W comes from prefix sums P,Q of the
// doubled row s2[j] = s[j mod 729]:
//   W[n] = (n+729)(P[n+730]-P[n+365]) - (Q[n+730]-Q[n+365])
//        + (Q[n+365]-Q[n+1]) - n(P[n+365]-P[n+1])
// One block per row; block-wide (P,Q) scan of 1458 elements.
// ---------------------------------------------------------------------------
__global__ void __launch_bounds__(256) k_filter(const float* __restrict__ sino) {
    __shared__ float2 pq_sh[1459];     // pq_sh[k] = (P[k], Q[k]), k = 0..1458
    __shared__ float2 wsum_sh[8];

    int tid = threadIdx.x, lane = tid & 31, wid = tid >> 5;
    const float* src = sino + blockIdx.x * ND;

    // local inclusive prefix over this thread's 6 elements
    int j0 = tid * 6;
    float2 loc[6];
    float p = 0.f, q = 0.f;
    #pragma unroll
    for (int k = 0; k < 6; k++) {
        int j = j0 + k;
        float v = 0.f;
        if (j < 2 * ND) v = __ldg(src + (j < ND ? j : j - ND));
        p += v;
        q = fmaf((float)j, v, q);
        loc[k] = make_float2(p, q);
    }
    float tp = p, tq = q;  // thread totals

    // warp inclusive scan of thread totals
    #pragma unroll
    for (int o = 1; o < 32; o <<= 1) {
        float ax = __shfl_up_sync(0xffffffffu, p, o);
        float aq = __shfl_up_sync(0xffffffffu, q, o);
        if (lane >= o) { p += ax; q += aq; }
    }
    if (lane == 31) wsum_sh[wid] = make_float2(p, q);
    __syncthreads();

    float wx = 0.f, wq = 0.f;
    #pragma unroll
    for (int w = 0; w < 8; w++)
        if (w < wid) { wx += wsum_sh[w].x; wq += wsum_sh[w].y; }

    float ex = wx + p - tp;   // exclusive prefix for this thread
    float eq = wq + q - tq;

    if (tid == 0) pq_sh[0] = make_float2(0.f, 0.f);
    #pragma unroll
    for (int k = 0; k < 6; k++) {
        int j = j0 + k;
        if (j < 2 * ND) pq_sh[j + 1] = make_float2(ex + loc[k].x, eq + loc[k].y);
    }
    __syncthreads();

    float T = pq_sh[ND].x;
    const float c0T = T * (1.0f / 5832.0f);        // T / (8*729)
    const float c1  = 1.0f / 1062882.0f;           // 1 / (1458*729)
    float* dst = g_filt + blockIdx.x * ND;
    for (int n = tid; n < ND; n += 256) {
        float2 A = pq_sh[n + 1], B = pq_sh[n + 365], C = pq_sh[n + 730];
        float W = (float)(n + 729) * (C.x - B.x) - (C.y - B.y)
                + (B.y - A.y) - (float)n * (B.x - A.x);
        dst[n] = fmaf(c1, W, c0T);
    }
}

// ---------------------------------------------------------------------------
// Kernel 2: trig tables + angle prefix sums of f[.,0] and f[.,728].
// ---------------------------------------------------------------------------
__global__ void __launch_bounds__(256) k_mid() {
    __shared__ float4 v[NA];
    int tid = threadIdx.x;
    if (tid < NA) {
        double ang = (double)tid * (PI_D / 179.0);
        double S = 729.0 / (2.0 * PI_D);
        g_cs[tid] = make_float2((float)(cos(ang) * S), (float)(sin(ang) * S));
        const float* f = g_filt;
        v[tid] = make_float4(f[tid * ND], f[tid * ND + 728],
                             f[(NA + tid) * ND], f[(NA + tid) * ND + 728]);
    }
    __syncthreads();
    for (int off = 1; off < NA; off <<= 1) {
        float4 a = make_float4(0.f, 0.f, 0.f, 0.f);
        bool act = (tid < NA && tid >= off);
        if (act) a = v[tid - off];
        __syncthreads();
        if (act) { v[tid].x += a.x; v[tid].y += a.y; v[tid].z += a.z; v[tid].w += a.w; }
        __syncthreads();
    }
    if (tid <= NA) {
        float4 e = (tid == 0) ? make_float4(0.f, 0.f, 0.f, 0.f) : v[tid - 1];
        g_P0[0][tid] = e.x; g_P7[0][tid] = e.y;
        g_P0[1][tid] = e.z; g_P7[1][tid] = e.w;
    }
}

// ---------------------------------------------------------------------------
// Kernel 3: backprojection with angular window + clip prefix sums.
// t(a) = fma(yc, sinS, xc*cosS) = rS * cos(theta_a - phi).  |t| < 729 only
// within Delta of a zero of cos(theta - phi); zeros at theta* and theta*+-pi
// (second window appears when theta* within Delta of 0 or pi, because the
// angle grid spans [0, pi] inclusive). Outside windows, idx clips to 0/728
// with constant sign per segment -> prefix-sum lookups.
// ---------------------------------------------------------------------------
struct Acc { float e0, e1; };

__device__ __forceinline__ void exact_range(int lo, int hi, float xc, float yc,
                                            const float2* cs,
                                            const float* __restrict__ f0,
                                            const float* __restrict__ f1,
                                            Acc& ac) {
    for (int a = lo; a <= hi; a++) {
        float2 t2 = cs[a];
        float t = fmaf(yc, t2.y, xc * t2.x);
        t = fminf(fmaxf(t, 0.f), 728.f);
        int idx = (int)t;
        ac.e0 += __ldg(f0 + a * ND + idx);
        ac.e1 += __ldg(f1 + a * ND + idx);
    }
}

// add clip-sum over a in [lo, hi]; sign sampled at angle a_s (outside windows)
__device__ __forceinline__ void clip_range(int lo, int hi, int a_s,
                                           float xc, float yc, const float2* cs,
                                           Acc& ac) {
    if (lo > hi) return;
    float2 t2 = cs[a_s];
    float t = fmaf(yc, t2.y, xc * t2.x);
    if (t > 0.f) {
        ac.e0 += __ldg(&g_P7[0][hi + 1]) - __ldg(&g_P7[0][lo]);
        ac.e1 += __ldg(&g_P7[1][hi + 1]) - __ldg(&g_P7[1][lo]);
    } else {
        ac.e0 += __ldg(&g_P0[0][hi + 1]) - __ldg(&g_P0[0][lo]);
        ac.e1 += __ldg(&g_P0[1][hi + 1]) - __ldg(&g_P0[1][lo]);
    }
}

__global__ void __launch_bounds__(256) k_backproj(float* __restrict__ out) {
    __shared__ float2 cs[NA];
    for (int i = threadIdx.x; i < NA; i += 256) cs[i] = g_cs[i];
    __syncthreads();

    int gid = blockIdx.x * 256 + threadIdx.x;   // 0..262143
    int x = gid & (NW - 1);
    int y = gid >> 9;
    float xc = (float)x - 256.0f;
    float yc = (float)y - 256.0f;

    const float* f0 = g_filt;
    const float* f1 = g_filt + NA * ND;
    Acc ac; ac.e0 = 0.f; ac.e1 = 0.f;

    const float S = (float)(729.0 / (2.0 * PI_D));
    float rS = sqrtf(xc * xc + yc * yc) * S;

    if (rS < 1500.0f) {
        exact_range(0, NA - 1, xc, yc, cs, f0, f1, ac);
    } else {
        float phi = atan2f(yc, xc);
        float ts = phi + (float)(PI_D * 0.5);
        if (ts < 0.f) ts += (float)PI_D;
        else if (ts > (float)PI_D) ts -= (float)PI_D;
        float delta = fmaf(729.0f / rS, 1.1f, 0.01f);
        const float inv_step = (float)(179.0 / PI_D);
        int aL = (int)floorf((ts - delta) * inv_step) - 1;
        int aH = (int)ceilf((ts + delta) * inv_step) + 1;

        if (aL <= 0 && aH >= NA - 1) {
            exact_range(0, NA - 1, xc, yc, cs, f0, f1, ac);
        } else if (aL >= 0 && aH <= NA - 1) {
            exact_range(aL, aH, xc, yc, cs, f0, f1, ac);
            if (aL > 0)      clip_range(0, aL - 1, 0, xc, yc, cs, ac);
            if (aH < NA - 1) clip_range(aH + 1, NA - 1, NA - 1, xc, yc, cs, ac);
        } else if (aL < 0) {
            // windows [0, aH] and [aL+179, 179]; middle (aH, aL+179)
            int w1 = aH;             // >= 0 here
            int w2 = aL + (NA - 1);  // <= 178
            if (w2 <= w1 + 1) {
                exact_range(0, NA - 1, xc, yc, cs, f0, f1, ac);
            } else {
                exact_range(0, w1, xc, yc, cs, f0, f1, ac);
                exact_range(w2, NA - 1, xc, yc, cs, f0, f1, ac);
                clip_range(w1 + 1, w2 - 1, w1 + 1, xc, yc, cs, ac);
            }
        } else {
            // aH > 179: windows [0, aH-179] and [aL, 179]; middle between
            int w1 = aH - (NA - 1);  // >= 1
            int w2 = aL;             // <= 179
            if (w2 <= w1 + 1) {
                exact_range(0, NA - 1, xc, yc, cs, f0, f1, ac);
            } else {
                exact_range(0, w1, xc, yc, cs, f0, f1, ac);
                exact_range(w2, NA - 1, xc, yc, cs, f0, f1, ac);
                clip_range(w1 + 1, w2 - 1, w1 + 1, xc, yc, cs, ac);
            }
        }
    }

    const float scale = (float)(PI_D / (double)NA);
    int p = y * NW + x;
    out[p] = fmaxf(ac.e0 * scale, 0.f);
    out[NH * NW + p] = fmaxf(ac.e1 * scale, 0.f);
}

// ---------------------------------------------------------------------------
extern "C" void kernel_launch(void* const* d_in, const int* in_sizes, int n_in,
                              void* d_out, int out_size) {
    const float* sino = (const float*)d_in[0];
    float* out = (float*)d_out;

    k_filter<<<NB * NA, 256>>>(sino);
    k_mid<<<1, 256>>>();
    k_backproj<<<(NH * NW) / 256, 256>>>(out);
}

// round 7
// speedup vs baseline: 4.3132x; 1.1980x over previous
#include <cuda_runtime.h>
#include <cstdint>

#define ND 729
#define NA 180
#define NB 2
#define NH 512
#define NW 512
#define PI_D 3.141592653589793

// Scratch (no cudaMalloc allowed)
__device__ float2 g_filt2[NA * ND];    // batch-interleaved: [a][d] -> (b0, b1)
__device__ float2 g_cs[NA];            // (cos*S, sin*S), S = 729/(2*pi)
__device__ float4 g_edge[NA];          // {f0_b0, f728_b0, f0_b1, f728_b1}

// ---------------------------------------------------------------------------
// Kernel 1: filter via closed-form piecewise-linear conv kernel
//   h(d) = (1/729)*(1/8 + min(d,729-d)/1458)
// using prefix sums over the SINGLE row; doubled-array prefixes reconstructed:
//   j<=729: P2=P[j], Q2=Q[j]
//   j> 729: P2=T+P[j-729], Q2=Q729+Q[j-729]+729*P[j-729]
// out[n] = c0*T + c1*W[n],
//   W[n] = (n+729)(P2[n+730]-P2[n+365]) - (Q2[n+730]-Q2[n+365])
//        + (Q2[n+365]-Q2[n+1]) - n(P2[n+365]-P2[n+1])
// Also emits g_edge[a] (columns 0 and 728) and g_cs (blocks with b==0).
// 360 blocks x 128 threads -> single wave.
// ---------------------------------------------------------------------------
__global__ void __launch_bounds__(128) k_filter(const float* __restrict__ sino) {
    __shared__ float  s_sh[768];
    __shared__ float2 pq[730];
    __shared__ float2 wsum[4];

    int tid = threadIdx.x, lane = tid & 31, wid = tid >> 5;
    int row = blockIdx.x;
    int b = (row >= NA) ? 1 : 0;
    int a = row - b * NA;
    const float* src = sino + row * ND;

    for (int i = tid; i < 768; i += 128) s_sh[i] = (i < ND) ? __ldg(src + i) : 0.f;
    __syncthreads();

    // local inclusive prefix over 6 contiguous elements
    int j0 = tid * 6;
    float2 loc[6];
    float p = 0.f, q = 0.f;
    #pragma unroll
    for (int k = 0; k < 6; k++) {
        int j = j0 + k;
        float v = s_sh[j];
        p += v;
        q = fmaf((float)j, v, q);
        loc[k] = make_float2(p, q);
    }
    float tp = p, tq = q;

    #pragma unroll
    for (int o = 1; o < 32; o <<= 1) {
        float ax = __shfl_up_sync(0xffffffffu, p, o);
        float aq = __shfl_up_sync(0xffffffffu, q, o);
        if (lane >= o) { p += ax; q += aq; }
    }
    if (lane == 31) wsum[wid] = make_float2(p, q);
    __syncthreads();

    float wx = 0.f, wq = 0.f;
    #pragma unroll
    for (int w = 0; w < 4; w++)
        if (w < wid) { wx += wsum[w].x; wq += wsum[w].y; }
    float ex = wx + p - tp, eq = wq + q - tq;

    if (tid == 0) pq[0] = make_float2(0.f, 0.f);
    #pragma unroll
    for (int k = 0; k < 6; k++) {
        int j = j0 + k;
        if (j < ND) pq[j + 1] = make_float2(ex + loc[k].x, eq + loc[k].y);
    }
    __syncthreads();

    float T = pq[ND].x, Q9 = pq[ND].y;
    const float c0T = T * (1.0f / 5832.0f);
    const float c1  = 1.0f / 1062882.0f;

    float* fdst = (float*)g_filt2;
    for (int n = tid; n < ND; n += 128) {
        // gather doubled prefixes at n+1, n+365, n+730
        float2 A = pq[n + 1];
        float2 B;
        if (n + 365 <= ND) B = pq[n + 365];
        else { float2 r = pq[n + 365 - ND]; B = make_float2(T + r.x, Q9 + r.y + 729.f * r.x); }
        float2 C;
        { float2 r = pq[n + 1]; C = make_float2(T + r.x, Q9 + r.y + 729.f * r.x); }  // n+730-729 = n+1
        float W = (float)(n + 729) * (C.x - B.x) - (C.y - B.y)
                + (B.y - A.y) - (float)n * (B.x - A.x);
        float f = fmaf(c1, W, c0T);
        fdst[(a * ND + n) * 2 + b] = f;
        if (n == 0)   ((float*)(g_edge + a))[2 * b + 0] = f;
        if (n == 728) ((float*)(g_edge + a))[2 * b + 1] = f;
    }

    if (tid == 0 && b == 0) {
        double ang = (double)a * (PI_D / 179.0);
        double S = 729.0 / (2.0 * PI_D);
        g_cs[a] = make_float2((float)(cos(ang) * S), (float)(sin(ang) * S));
    }
}

// ---------------------------------------------------------------------------
// Kernel 2: backprojection. Warp = 8x4 pixel tile (minimizes phi spread ->
// window divergence). Each block first builds the 4-channel exclusive prefix
// over angles of g_edge (warp 0, ~300cyc). Gathers are batch-interleaved
// LDG.64. Window: |t|<728.5 only within asin(728.5/rS)*1.05+0.004 of a zero
// of cos(theta-phi); outside, idx clips with constant sign per segment.
// ---------------------------------------------------------------------------
__device__ __forceinline__ void exact_range(int lo, int hi, float xc, float yc,
                                            const float2* cs, float& e0, float& e1) {
    const float2* f2 = (const float2*)g_filt2;
    for (int a = lo; a <= hi; a++) {
        float2 t2 = cs[a];
        float t = fmaf(yc, t2.y, xc * t2.x);
        t = fminf(fmaxf(t, 0.f), 728.f);
        int idx = (int)t;
        float2 v = __ldg(f2 + a * ND + idx);
        e0 += v.x;
        e1 += v.y;
    }
}

__global__ void __launch_bounds__(256) k_backproj(float* __restrict__ out) {
    __shared__ float2 cs[NA];
    __shared__ float4 pre[NA + 1];

    int tid = threadIdx.x;
    for (int i = tid; i < NA; i += 256) cs[i] = g_cs[i];
    if (tid < 32) {
        // warp-0 scan of g_edge -> pre[0..180] (exclusive->inclusive hybrid)
        float4 acc = make_float4(0.f, 0.f, 0.f, 0.f);
        float4 loc[6];
        #pragma unroll
        for (int k = 0; k < 6; k++) {
            int a2 = tid * 6 + k;
            float4 v = (a2 < NA) ? __ldg(g_edge + a2) : make_float4(0.f, 0.f, 0.f, 0.f);
            acc.x += v.x; acc.y += v.y; acc.z += v.z; acc.w += v.w;
            loc[k] = acc;
        }
        float4 tot = acc;
        #pragma unroll
        for (int o = 1; o < 32; o <<= 1) {
            float ax = __shfl_up_sync(0xffffffffu, acc.x, o);
            float ay = __shfl_up_sync(0xffffffffu, acc.y, o);
            float az = __shfl_up_sync(0xffffffffu, acc.z, o);
            float aw = __shfl_up_sync(0xffffffffu, acc.w, o);
            if (tid >= o) { acc.x += ax; acc.y += ay; acc.z += az; acc.w += aw; }
        }
        float4 excl = make_float4(acc.x - tot.x, acc.y - tot.y, acc.z - tot.z, acc.w - tot.w);
        #pragma unroll
        for (int k = 0; k < 6; k++) {
            int a2 = tid * 6 + k;
            if (a2 < NA)
                pre[a2 + 1] = make_float4(excl.x + loc[k].x, excl.y + loc[k].y,
                                          excl.z + loc[k].z, excl.w + loc[k].w);
        }
        if (tid == 0) pre[0] = make_float4(0.f, 0.f, 0.f, 0.f);
    }
    __syncthreads();

    // 8x4 lane tile, 2x4 warp tiles -> 16x16 block tile; 32x32 blocks
    int lane = tid & 31, w = tid >> 5;
    int x = ((int)blockIdx.x & 31) * 16 + (w & 1) * 8 + (lane & 7);
    int y = ((int)blockIdx.x >> 5) * 16 + (w >> 1) * 4 + (lane >> 3);
    float xc = (float)x - 256.0f;
    float yc = (float)y - 256.0f;

    float e0 = 0.f, e1 = 0.f;
    const float S = (float)(729.0 / (2.0 * PI_D));
    float rS = sqrtf(xc * xc + yc * yc) * S;

    // clip-sum helper via lambda-ish macro on pre[]
    #define CLIP_RANGE(lo, hi, a_s)                                           \
        do {                                                                  \
            float2 t2s = cs[a_s];                                             \
            float ts_ = fmaf(yc, t2s.y, xc * t2s.x);                          \
            float4 Hi = pre[(hi) + 1], Lo = pre[lo];                          \
            if (ts_ > 0.f) { e0 += Hi.y - Lo.y; e1 += Hi.w - Lo.w; }          \
            else           { e0 += Hi.x - Lo.x; e1 += Hi.z - Lo.z; }          \
        } while (0)

    if (rS < 1500.0f) {
        exact_range(0, NA - 1, xc, yc, cs, e0, e1);
    } else {
        float phi = atan2f(yc, xc);
        float ts = phi + (float)(PI_D * 0.5);
        if (ts < 0.f) ts += (float)PI_D;
        else if (ts > (float)PI_D) ts -= (float)PI_D;
        float delta = fmaf(728.5f / rS, 1.05f, 0.004f);
        const float inv_step = (float)(179.0 / PI_D);
        int aL = (int)floorf((ts - delta) * inv_step);
        int aH = (int)ceilf((ts + delta) * inv_step);

        if (aL <= 0 && aH >= NA - 1) {
            exact_range(0, NA - 1, xc, yc, cs, e0, e1);
        } else if (aL >= 0 && aH <= NA - 1) {
            exact_range(aL, aH, xc, yc, cs, e0, e1);
            if (aL > 0)      CLIP_RANGE(0, aL - 1, 0);
            if (aH < NA - 1) CLIP_RANGE(aH + 1, NA - 1, NA - 1);
        } else if (aL < 0) {
            int w1 = aH;             // window [0, w1]
            int w2 = aL + (NA - 1);  // window [w2, 179]
            if (w2 <= w1 + 1) {
                exact_range(0, NA - 1, xc, yc, cs, e0, e1);
            } else {
                exact_range(0, w1, xc, yc, cs, e0, e1);
                exact_range(w2, NA - 1, xc, yc, cs, e0, e1);
                CLIP_RANGE(w1 + 1, w2 - 1, w1 + 1);
            }
        } else {
            int w1 = aH - (NA - 1);  // window [0, w1]
            int w2 = aL;             // window [w2, 179]
            if (w2 <= w1 + 1) {
                exact_range(0, NA - 1, xc, yc, cs, e0, e1);
            } else {
                exact_range(0, w1, xc, yc, cs, e0, e1);
                exact_range(w2, NA - 1, xc, yc, cs, e0, e1);
                CLIP_RANGE(w1 + 1, w2 - 1, w1 + 1);
            }
        }
    }
    #undef CLIP_RANGE

    const float scale = (float)(PI_D / (double)NA);
    int p = y * NW + x;
    out[p] = fmaxf(e0 * scale, 0.f);
    out[NH * NW + p] = fmaxf(e1 * scale, 0.f);
}

// ---------------------------------------------------------------------------
extern "C" void kernel_launch(void* const* d_in, const int* in_sizes, int n_in,
                              void* d_out, int out_size) {
    const float* sino = (const float*)d_in[0];
    float* out = (float*)d_out;

    k_filter<<<NB * NA, 128>>>(sino);
    k_backproj<<<1024, 256>>>(out);
}